// round 13
// baseline (speedup 1.0000x reference)
#include <cuda_runtime.h>
#include <math.h>
#include <stdint.h>

#define BATCH 4
#define TSTEPS 8
#define HC 64
#define HW 4096
#define CHW (HC*HW)            // 262144
#define NB (BATCH*HC*HW)       // 1048576

typedef unsigned long long u64;

// ---------------- f32x2 packed helpers ----------------
__device__ __forceinline__ u64 pk2(float lo, float hi){
  u64 r; asm("mov.b64 %0, {%1,%2};" : "=l"(r) : "f"(lo), "f"(hi)); return r;
}
__device__ __forceinline__ u64 dup2(float v){
  u64 r; asm("mov.b64 %0, {%1,%1};" : "=l"(r) : "f"(v)); return r;
}
__device__ __forceinline__ void fma2(u64 &acc, u64 a, u64 b){
  asm("fma.rn.f32x2 %0, %1, %2, %0;" : "+l"(acc) : "l"(a), "l"(b));
}
__device__ __forceinline__ float2 upk(u64 v){
  float2 f; asm("mov.b64 {%0,%1}, %2;" : "=f"(f.x), "=f"(f.y) : "l"(v)); return f;
}
// ---------------- cp.async helpers ----------------
__device__ __forceinline__ void cpa16(uint32_t saddr, const float* g, int nbytes){
  asm volatile("cp.async.cg.shared.global [%0], [%1], 16, %2;"
               :: "r"(saddr), "l"(g), "r"(nbytes) : "memory");
}
__device__ __forceinline__ void cpcommit(){ asm volatile("cp.async.commit_group;" ::: "memory"); }
__device__ __forceinline__ void cpwait1(){ asm volatile("cp.async.wait_group 1;" ::: "memory"); }
__device__ __forceinline__ void cpwait0(){ asm volatile("cp.async.wait_group 0;" ::: "memory"); }

// ---------------- device scratch (static) ----------------
__device__ float g_h0[NB];
__device__ float g_c0[NB];
__device__ float g_c1[NB];
__device__ float g_m[NB];
__device__ float g_rc[NB], g_xm[NB];
__device__ float g_r[NB], g_z[NB], g_o[NB], g_xr[NB], g_xz[NB];
__device__ float g_gct[NB], g_gmt[NB];
__device__ float g_q[NB], g_k[NB];
__device__ float g_attn[BATCH*64*64];
__device__ float g_hs[BATCH*TSTEPS*HC*HW];
__device__ float g_zero[NB];   // NEVER written -> stays zero

__device__ __forceinline__ float sigf(float x){ return 1.f/(1.f+expf(-x)); }

__global__ void tg_zero_states(){
  int i = blockIdx.x*256 + threadIdx.x;
  if (i < NB){ g_h0[i]=0.f; g_c0[i]=0.f; g_c1[i]=0.f; g_m[i]=0.f; }
}

// ---------------- merged dual-stream 3x3 conv with FUSED pointwise epilogue ------
// (R8 geometry; PDL prologue/gridsync; launch_bounds (128,6) for +1 block/SM)
// Block 128 thr = 8 rows x 16 colgroups(4px). Each thread: 4 px x 8 oc (4 oc-pairs).
#define CC 4
__global__ void __launch_bounds__(128,6) tg_conv3x3(
    const float* __restrict__ in0, int C0, long bs0,
    const float* __restrict__ in1A, long bs1A,
    const float* __restrict__ in1B, long bs1B,
    const float* __restrict__ wA, const float* __restrict__ bA,
    const float* __restrict__ wB, const float* __restrict__ bB,
    int nA8, int Cin, int mode,
    const float* __restrict__ hp, long hbs,
    float* __restrict__ cbuf,
    const float* __restrict__ tgp, const float* __restrict__ tdh,
    const float* __restrict__ tdm)
{
  __shared__ __align__(16) float tile[3][CC][720];   // 10 rows x 72 cols, px0 at col 4
  __shared__ __align__(16) u64   ws[2][CC][4][12];   // [pair][ky][kx(pad4)] oc-pair packed

  const int tid = threadIdx.x;
  const int b   = blockIdx.z;
  int ocb = blockIdx.y;
  const int ty = tid >> 4;          // 0..7
  const int tx = (tid & 15) * 4;    // 0..60
  const int y0 = blockIdx.x * 8;

  const int isA = (ocb < nA8);
  const float* in1; const float* w; const float* bias;
  long bs1;
  if (isA){ in1=in1A; bs1=bs1A; w=wA; bias=bA; }
  else { ocb-=nA8; in1=in1B; bs1=bs1B; w=wB; bias=bB; }

  const float* pin0 = in0 + (long)b*bs0;
  const float* pin1 = in1 + (long)b*bs1;

  // ===== independent prologue (const inputs + smem only) =====
  for (int i=tid; i<240; i+=128){
    int buf = i/80; int rem = i-buf*80; int ci = rem/20; int rr = rem-ci*20;
    int r = rr>>1; int side = rr&1;
    tile[buf][ci][r*72 + (side?68:3)] = 0.f;
  }

  // weight slot descriptors (144 u64 per chunk, 2 slots/thread)
  int wex[2], woff[2], wsts[2];
#pragma unroll
  for (int s=0;s<2;s++){
    int j = tid + s*128;
    wex[s] = (j < 144);
    int jj = wex[s] ? j : 0;
    int ci = jj/36; int rem = jj - ci*36; int p = rem/9; int k = rem - p*9;
    int oc0 = ocb*8 + 2*p;
    woff[s] = (oc0*Cin + ci)*9 + k;
    wsts[s] = (((ci*4)+p)*12 + (k/3)*4 + (k%3))*8;
  }
  const int nch = Cin/CC;
  const int wsBufBytes = CC*4*12*8;  // 1536
  char* wsb = (char*)&ws[0][0][0][0];
  uint32_t tbase = (uint32_t)__cvta_generic_to_shared(&tile[0][0][0]);

  // interior tile slots: 160 16B ops per cin, CC*160 = 640 per chunk, 5/thread exactly
  int sci[5], sso[5], sgo[5];
#pragma unroll
  for (int s=0;s<5;s++){
    int idx = tid + s*128;          // 0..639
    int ci  = idx / 160;
    int rem = idx - ci*160;
    int row = rem >> 4;
    int seg = rem & 15;
    int gy  = y0 + row - 1;
    sci[s] = ci;
    sso[s] = ci*2880 + (row*72 + 4 + seg*4)*4;
    sgo[s] = (gy>=0 && gy<64) ? (gy*64 + seg*4) : -1;
  }

  u64 acc[4][4];
#pragma unroll
  for (int p=0;p<4;p++){
    u64 bb = pk2(bias[ocb*8+2*p], bias[ocb*8+2*p+1]);
#pragma unroll
    for (int px=0;px<4;px++) acc[p][px] = bb;
  }

  // weights are const inputs -> safe before gridsync
  float wh[2][2];
#pragma unroll
  for (int s=0;s<2;s++) if (wex[s]){   // chunk 0 weights: LDG + STS now
    float a0 = w[woff[s]];
    float a1 = w[woff[s] + Cin*9];
    *(u64*)(wsb + wsts[s]) = pk2(a0, a1);
  }
#pragma unroll
  for (int s=0;s<2;s++) if (wex[s]){   // chunk 1 weights: LDG, hold
    wh[s][0] = w[woff[s] + 9*CC];
    wh[s][1] = w[woff[s] + 9*CC + Cin*9];
  }

  // ===== wait for predecessor kernel's data =====
  cudaGridDependencySynchronize();

  // ---- dependent prologue: tile chunks 0,1 ----
#pragma unroll 1
  for (int cc=0; cc<2; cc++){
#pragma unroll
    for (int s=0;s<5;s++){
      int cing = cc*CC + sci[s];
      const float* src = (cing < C0) ? pin0 + (long)cing*HW
                                     : pin1 + (long)(cing-C0)*HW;
      cpa16(tbase + (uint32_t)(cc*11520) + sso[s],
            src + (sgo[s]>=0 ? sgo[s] : 0), sgo[s]>=0 ? 16 : 0);
    }
    cpcommit();
  }

  // ---- main pipeline ----
  for (int c=0; c<nch; c++){
    if (c+1 < nch) cpwait1(); else cpwait0();
    __syncthreads();
    if (c+1 < nch){
#pragma unroll
      for (int s=0;s<2;s++) if (wex[s])
        *(u64*)(wsb + ((c+1)&1)*wsBufBytes + wsts[s]) = pk2(wh[s][0], wh[s][1]);
    }
    if (c+2 < nch){
#pragma unroll
      for (int s=0;s<2;s++) if (wex[s]){
        wh[s][0] = w[woff[s] + (c+2)*9*CC];
        wh[s][1] = w[woff[s] + (c+2)*9*CC + Cin*9];
      }
      int buf = (c+2)%3;
#pragma unroll
      for (int s=0;s<5;s++){
        int cing = (c+2)*CC + sci[s];
        const float* src = (cing < C0) ? pin0 + (long)cing*HW
                                       : pin1 + (long)(cing-C0)*HW;
        cpa16(tbase + (uint32_t)(buf*11520) + sso[s],
              src + (sgo[s]>=0 ? sgo[s] : 0), sgo[s]>=0 ? 16 : 0);
      }
      cpcommit();
    }
    // compute chunk c
    const int tb = c%3, wb = c&1;
#pragma unroll
    for (int ci=0;ci<CC;ci++){
#pragma unroll
      for (int r=0;r<3;r++){
        const float* row = &tile[tb][ci][(ty+r)*72 + tx + 3];
        float v0 = row[0];
        float4 vm = *reinterpret_cast<const float4*>(row+1);
        float v5 = row[5];
        u64 pv0=dup2(v0), pv1=dup2(vm.x), pv2=dup2(vm.y),
            pv3=dup2(vm.z), pv4=dup2(vm.w), pv5=dup2(v5);
#pragma unroll
        for (int p=0;p<4;p++){
          ulonglong2 w01 = *reinterpret_cast<const ulonglong2*>(&ws[wb][ci][p][r*4]);
          u64 w2 = ws[wb][ci][p][r*4+2];
          fma2(acc[p][0], w01.x, pv0); fma2(acc[p][0], w01.y, pv1); fma2(acc[p][0], w2, pv2);
          fma2(acc[p][1], w01.x, pv1); fma2(acc[p][1], w01.y, pv2); fma2(acc[p][1], w2, pv3);
          fma2(acc[p][2], w01.x, pv2); fma2(acc[p][2], w01.y, pv3); fma2(acc[p][2], w2, pv4);
          fma2(acc[p][3], w01.x, pv3); fma2(acc[p][3], w01.y, pv4); fma2(acc[p][3], w2, pv5);
        }
      }
    }
  }

  // ---- fused epilogue ----
  const long pixb = (long)(y0+ty)*64 + tx;
  const int seg = ocb >> 3;
#pragma unroll
  for (int p=0;p<4;p++){
    float2 a0=upk(acc[p][0]), a1=upk(acc[p][1]), a2=upk(acc[p][2]), a3=upk(acc[p][3]);
    float av[2][4] = {{a0.x,a1.x,a2.x,a3.x},{a0.y,a1.y,a2.y,a3.y}};
#pragma unroll
    for (int k=0;k<2;k++){
      int oc = ocb*8 + 2*p + k;
      int ch = oc & 63;
      long idx = (long)b*CHW + (long)ch*HW + pixb;
      if (mode == 0){
        if (isA){
          if (seg < 2){
            float gate = sigf(tgp[ch]);
            float dh = expf(-tdh[ch]);
            float4 hv = *reinterpret_cast<const float4*>(&hp[(long)b*hbs + (long)ch*HW + pixb]);
            float4 g;
            g.x = sigf(av[k][0]*gate + hv.x*dh);
            g.y = sigf(av[k][1]*gate + hv.y*dh);
            g.z = sigf(av[k][2]*gate + hv.z*dh);
            g.w = sigf(av[k][3]*gate + hv.w*dh);
            if (seg == 0){
              *reinterpret_cast<float4*>(&g_r[idx]) = g;
              float4 cv = *reinterpret_cast<const float4*>(&cbuf[idx]);
              *reinterpret_cast<float4*>(&g_rc[idx]) =
                make_float4(g.x*cv.x, g.y*cv.y, g.z*cv.z, g.w*cv.w);
            } else {
              *reinterpret_cast<float4*>(&g_z[idx]) = g;
            }
          } else {
            *reinterpret_cast<float4*>(&g_o[idx]) =
              make_float4(sigf(av[k][0]), sigf(av[k][1]), sigf(av[k][2]), sigf(av[k][3]));
          }
        } else {
          float gate = sigf(tgp[ch]);
          float dm = expf(-tdm[ch]);
          float4 mv = *reinterpret_cast<const float4*>(&g_m[idx]);
          float4 g;
          g.x = sigf(av[k][0]*gate + mv.x*dm);
          g.y = sigf(av[k][1]*gate + mv.y*dm);
          g.z = sigf(av[k][2]*gate + mv.z*dm);
          g.w = sigf(av[k][3]*gate + mv.w*dm);
          if (seg == 0){
            *reinterpret_cast<float4*>(&g_xr[idx]) = g;
            *reinterpret_cast<float4*>(&g_xm[idx]) =
              make_float4(g.x*mv.x, g.y*mv.y, g.z*mv.z, g.w*mv.w);
          } else {
            *reinterpret_cast<float4*>(&g_xz[idx]) = g;
          }
        }
      } else {
        float4 tc = make_float4(tanhf(av[k][0]), tanhf(av[k][1]),
                                tanhf(av[k][2]), tanhf(av[k][3]));
        if (isA){
          float4 zv = *reinterpret_cast<const float4*>(&g_z[idx]);
          float4 cv = *reinterpret_cast<const float4*>(&cbuf[idx]);
          float4 cn;
          cn.x = zv.x*cv.x + (1.f-zv.x)*tc.x;
          cn.y = zv.y*cv.y + (1.f-zv.y)*tc.y;
          cn.z = zv.z*cv.z + (1.f-zv.z)*tc.z;
          cn.w = zv.w*cv.w + (1.f-zv.w)*tc.w;
          *reinterpret_cast<float4*>(&cbuf[idx]) = cn;
          *reinterpret_cast<float4*>(&g_gct[idx]) = tc;
        } else {
          float4 xzv = *reinterpret_cast<const float4*>(&g_xz[idx]);
          float4 mv  = *reinterpret_cast<const float4*>(&g_m[idx]);
          float4 mn;
          mn.x = xzv.x*mv.x + (1.f-xzv.x)*tc.x;
          mn.y = xzv.y*mv.y + (1.f-xzv.y)*tc.y;
          mn.z = xzv.z*mv.z + (1.f-xzv.z)*tc.z;
          mn.w = xzv.w*mv.w + (1.f-xzv.w)*tc.w;
          *reinterpret_cast<float4*>(&g_m[idx]) = mn;
          *reinterpret_cast<float4*>(&g_gmt[idx]) = tc;
        }
      }
    }
  }
}

// ---------------- 1x1 conv (f32x2) with fused h = o*tanh(.) and optional q/k ----
// Block 256 thr, each thread 2 px x 4 oc. grid (8, BATCH, 16)
__global__ void __launch_bounds__(256) tg_conv1x1(
    const float* __restrict__ c,
    const float* __restrict__ w, const float* __restrict__ bias,
    float* __restrict__ out, long bsOut, int doQK)
{
  __shared__ u64 ws[4*128];
  const int tid = threadIdx.x;
  const int b   = blockIdx.y;
  const int ocg = blockIdx.z;   // group of 4 oc
  // independent prologue: weights are const inputs
  for (int i=tid;i<4*128;i+=256){
    float v = w[(long)(ocg*4)*128 + i];
    ws[i] = pk2(v,v);
  }
  u64 acc[4];
#pragma unroll
  for (int oc=0;oc<4;oc++){
    float bv = bias[ocg*4+oc];
    acc[oc] = pk2(bv,bv);
  }
  __syncthreads();
  cudaGridDependencySynchronize();

  const int pix = (blockIdx.x*256 + tid)*2;
  const long base = (long)b*CHW + pix;
#pragma unroll 8
  for (int cc=0;cc<64;cc++){
    u64 v0 = *reinterpret_cast<const u64*>(&c[base + (long)cc*HW]);
    u64 v1 = *reinterpret_cast<const u64*>(&g_m[base + (long)cc*HW]);
#pragma unroll
    for (int oc=0;oc<4;oc++){
      fma2(acc[oc], ws[oc*128+cc], v0);
      fma2(acc[oc], ws[oc*128+64+cc], v1);
    }
  }
#pragma unroll
  for (int oc=0;oc<4;oc++){
    int ocf = ocg*4+oc;
    long idx = base + (long)ocf*HW;
    float2 ov = *reinterpret_cast<const float2*>(&g_o[idx]);
    float2 a = upk(acc[oc]);
    float2 res;
    res.x = ov.x * tanhf(a.x);
    res.y = ov.y * tanhf(a.y);
    *reinterpret_cast<float2*>(&out[(long)b*bsOut + (long)ocf*HW + pix]) = res;
    if (doQK){
      float2 rv = *reinterpret_cast<const float2*>(&g_r[idx]);
      float2 xr = *reinterpret_cast<const float2*>(&g_xr[idx]);
      float2 cv = *reinterpret_cast<const float2*>(&c[idx]);
      float2 gc = *reinterpret_cast<const float2*>(&g_gct[idx]);
      float2 mv = *reinterpret_cast<const float2*>(&g_m[idx]);
      float2 gm = *reinterpret_cast<const float2*>(&g_gmt[idx]);
      float2 q, k2;
      q.x  = 0.25f*(rv.x + xr.x + cv.x + gc.x);
      q.y  = 0.25f*(rv.y + xr.y + cv.y + gc.y);
      k2.x = 0.25f*(rv.x + xr.x + mv.x + gm.x);
      k2.y = 0.25f*(rv.y + xr.y + mv.y + gm.y);
      *reinterpret_cast<float2*>(&g_q[idx]) = q;
      *reinterpret_cast<float2*>(&g_k[idx]) = k2;
    }
  }
}

// ---------------- attention logits + softmax ----------------
__global__ void tg_attn()
{
  __shared__ float qs[HW];
  __shared__ float red[2];
  __shared__ float logits[64];
  __shared__ float tmp[64];
  const int b = blockIdx.y, i = blockIdx.x, t = threadIdx.x;  // 64 threads
  cudaGridDependencySynchronize();
  const float* qrow = g_q + ((long)b*64 + i)*HW;
  for (int n=t;n<HW;n+=64) qs[n] = qrow[n];
  __syncthreads();
  for (int j=0;j<64;j++){
    const float* krow = g_k + ((long)b*64 + j)*HW;
    float s = 0.f;
    for (int n=t;n<HW;n+=64) s += qs[n]*krow[n];
#pragma unroll
    for (int off=16;off;off>>=1) s += __shfl_down_sync(0xffffffffu, s, off);
    if ((t&31)==0) red[t>>5] = s;
    __syncthreads();
    if (t==0) logits[j] = (red[0]+red[1]) * 0.015625f;
    __syncthreads();
  }
  float xv = logits[t];
  tmp[t] = xv; __syncthreads();
  for (int s2=32; s2; s2>>=1){ if (t<s2) tmp[t] = fmaxf(tmp[t], tmp[t+s2]); __syncthreads(); }
  float mx = tmp[0]; __syncthreads();
  float e = expf(xv - mx);
  tmp[t] = e; __syncthreads();
  for (int s2=32; s2; s2>>=1){ if (t<s2) tmp[t] += tmp[t+s2]; __syncthreads(); }
  g_attn[((long)b*64+i)*64 + t] = e / tmp[0];
}

// ---------------- apply attention ----------------
__global__ void __launch_bounds__(256) tg_apply(float* __restrict__ out)
{
  __shared__ float as[64*64];
  const int b = blockIdx.z, tt = blockIdx.y;
  const int n = blockIdx.x*256 + threadIdx.x;
  cudaGridDependencySynchronize();
  for (int i=threadIdx.x;i<4096;i+=256) as[i] = g_attn[(long)b*4096 + i];
  __syncthreads();
  float acc[64];
#pragma unroll
  for (int c=0;c<64;c++) acc[c]=0.f;
  const float* v = g_hs + (((long)b*TSTEPS + tt)*64)*HW + n;
  for (int d=0; d<64; d++){
    float vv = v[(long)d*HW];
#pragma unroll
    for (int c=0;c<64;c++) acc[c] += as[c*64+d]*vv;
  }
  float* op = out + (((long)b*TSTEPS + tt)*64)*HW + n;
#pragma unroll
  for (int c=0;c<64;c++) op[(long)c*HW] = acc[c];
}

// ---------------- PDL launch helper ----------------
template <typename F, typename... Args>
static inline void pdl(F fn, dim3 grid, dim3 block, Args... args)
{
  cudaLaunchConfig_t cfg = {};
  cfg.gridDim = grid;
  cfg.blockDim = block;
  cfg.dynamicSmemBytes = 0;
  cfg.stream = 0;   // legacy default stream (same as <<<>>>)
  cudaLaunchAttribute at[1];
  at[0].id = cudaLaunchAttributeProgrammaticStreamSerialization;
  at[0].val.programmaticStreamSerializationAllowed = 1;
  cfg.attrs = at;
  cfg.numAttrs = 1;
  cudaLaunchKernelEx(&cfg, fn, args...);
}

// ---------------- orchestration ----------------
extern "C" void kernel_launch(void* const* d_in, const int* in_sizes, int n_in,
                              void* d_out, int out_size)
{
  (void)in_sizes; (void)n_in; (void)out_size;
  const float* x      = (const float*)d_in[0];
  const float* w_rzo0 = (const float*)d_in[1];
  const float* b_rzo0 = (const float*)d_in[2];
  const float* w_rz0  = (const float*)d_in[3];
  const float* b_rz0  = (const float*)d_in[4];
  const float* w_h0   = (const float*)d_in[5];
  const float* b_h0   = (const float*)d_in[6];
  const float* w_o0   = (const float*)d_in[7];
  const float* b_o0   = (const float*)d_in[8];
  const float* td_h0  = (const float*)d_in[9];
  const float* td_m0  = (const float*)d_in[10];
  const float* tg0    = (const float*)d_in[11];
  const float* w_rzo1 = (const float*)d_in[12];
  const float* b_rzo1 = (const float*)d_in[13];
  const float* w_rz1  = (const float*)d_in[14];
  const float* b_rz1  = (const float*)d_in[15];
  const float* w_h1   = (const float*)d_in[16];
  const float* b_h1   = (const float*)d_in[17];
  const float* w_o1   = (const float*)d_in[18];
  const float* b_o1   = (const float*)d_in[19];
  const float* td_h1  = (const float*)d_in[20];
  const float* td_m1  = (const float*)d_in[21];
  const float* tg1    = (const float*)d_in[22];

  float *p_h0,*p_c0,*p_c1,*p_m,*p_rc,*p_xm,*p_hs,*p_zero;
  cudaGetSymbolAddress((void**)&p_h0,  g_h0);
  cudaGetSymbolAddress((void**)&p_c0,  g_c0);
  cudaGetSymbolAddress((void**)&p_c1,  g_c1);
  cudaGetSymbolAddress((void**)&p_m,   g_m);
  cudaGetSymbolAddress((void**)&p_rc,  g_rc);
  cudaGetSymbolAddress((void**)&p_xm,  g_xm);
  cudaGetSymbolAddress((void**)&p_hs,  g_hs);
  cudaGetSymbolAddress((void**)&p_zero,g_zero);

  const long nbs = (long)CHW;

  tg_zero_states<<<NB/256, 256>>>();

  for (int t=0; t<TSTEPS; t++){
    // ---------- layer 0 (Cin = 16+64 = 80) ----------
    const float* xt = x + (long)t*16*HW;
    const long xbs = (long)TSTEPS*16*HW;
    pdl(tg_conv3x3, dim3(8,40,BATCH), dim3(128),
        xt,16,xbs, p_h0,nbs, p_m,nbs,
        w_rzo0,b_rzo0, w_rz0,b_rz0, 24, 80, 0, (const float*)p_h0,nbs, p_c0,
        tg0, td_h0, td_m0);
    pdl(tg_conv3x3, dim3(8,16,BATCH), dim3(128),
        xt,16,xbs, (const float*)p_rc,nbs, (const float*)p_xm,nbs,
        w_h0,b_h0, w_h0,b_h0, 8, 80, 1, (const float*)p_zero,nbs, p_c0,
        tg0, td_h0, td_m0);
    pdl(tg_conv1x1, dim3(8,BATCH,16), dim3(256),
        (const float*)p_c0, w_o0, b_o0, p_h0, nbs, 0);

    // ---------- layer 1 (Cin = 64+64 = 128) ----------
    const float* h1p = (t==0) ? p_zero : (p_hs + (long)(t-1)*CHW);
    const long h1bs  = (t==0) ? nbs : (long)TSTEPS*CHW;
    pdl(tg_conv3x3, dim3(8,40,BATCH), dim3(128),
        (const float*)p_h0,64,nbs, h1p,h1bs, (const float*)p_m,nbs,
        w_rzo1,b_rzo1, w_rz1,b_rz1, 24, 128, 0, h1p,h1bs, p_c1,
        tg1, td_h1, td_m1);
    pdl(tg_conv3x3, dim3(8,16,BATCH), dim3(128),
        (const float*)p_h0,64,nbs, (const float*)p_rc,nbs, (const float*)p_xm,nbs,
        w_h1,b_h1, w_h1,b_h1, 8, 128, 1, (const float*)p_zero,nbs, p_c1,
        tg1, td_h1, td_m1);
    pdl(tg_conv1x1, dim3(8,BATCH,16), dim3(256),
        (const float*)p_c1, w_o1, b_o1, p_hs + (long)t*CHW,
        (long)TSTEPS*CHW, (t==TSTEPS-1) ? 1 : 0);
  }

  pdl(tg_attn, dim3(64,BATCH), dim3(64));
  pdl(tg_apply, dim3(16,TSTEPS,BATCH), dim3(256), (float*)d_out);
}

// round 14
// speedup vs baseline: 1.0300x; 1.0300x over previous
#include <cuda_runtime.h>
#include <math.h>
#include <stdint.h>

#define BATCH 4
#define TSTEPS 8
#define HC 64
#define HW 4096
#define CHW (HC*HW)            // 262144
#define NB (BATCH*HC*HW)       // 1048576

typedef unsigned long long u64;

// ---------------- f32x2 packed helpers ----------------
__device__ __forceinline__ u64 pk2(float lo, float hi){
  u64 r; asm("mov.b64 %0, {%1,%2};" : "=l"(r) : "f"(lo), "f"(hi)); return r;
}
__device__ __forceinline__ u64 dup2(float v){
  u64 r; asm("mov.b64 %0, {%1,%1};" : "=l"(r) : "f"(v)); return r;
}
__device__ __forceinline__ void fma2(u64 &acc, u64 a, u64 b){
  asm("fma.rn.f32x2 %0, %1, %2, %0;" : "+l"(acc) : "l"(a), "l"(b));
}
__device__ __forceinline__ float2 upk(u64 v){
  float2 f; asm("mov.b64 {%0,%1}, %2;" : "=f"(f.x), "=f"(f.y) : "l"(v)); return f;
}
// ---------------- cp.async helpers ----------------
__device__ __forceinline__ void cpa16(uint32_t saddr, const float* g, int nbytes){
  asm volatile("cp.async.cg.shared.global [%0], [%1], 16, %2;"
               :: "r"(saddr), "l"(g), "r"(nbytes) : "memory");
}
__device__ __forceinline__ void cpcommit(){ asm volatile("cp.async.commit_group;" ::: "memory"); }
__device__ __forceinline__ void cpwait1(){ asm volatile("cp.async.wait_group 1;" ::: "memory"); }
__device__ __forceinline__ void cpwait0(){ asm volatile("cp.async.wait_group 0;" ::: "memory"); }

// ---------------- device scratch (static) ----------------
__device__ float g_h0[NB];
__device__ float g_c0[NB];
__device__ float g_c1[NB];
__device__ float g_m[NB];
__device__ float g_rc[NB], g_xm[NB];
__device__ float g_r[NB], g_z[NB], g_xr[NB], g_xz[NB];
__device__ float g_o0[NB], g_o1[NB];     // per-layer o (enables stream overlap)
__device__ float g_gct[NB], g_gmt[NB];
__device__ float g_q[NB], g_k[NB];
__device__ float g_attn[BATCH*64*64];
__device__ float g_hs[BATCH*TSTEPS*HC*HW];
__device__ float g_zero[NB];   // NEVER written -> stays zero

__device__ __forceinline__ float sigf(float x){ return 1.f/(1.f+expf(-x)); }

__global__ void tg_zero_states(){
  int i = blockIdx.x*256 + threadIdx.x;
  if (i < NB){ g_h0[i]=0.f; g_c0[i]=0.f; g_c1[i]=0.f; g_m[i]=0.f; }
}

// ---------------- merged dual-stream 3x3 conv with FUSED pointwise epilogue ------
// (R8/R12 geometry; PDL prologue/gridsync; launch_bounds (128,5))
// Block 128 thr = 8 rows x 16 colgroups(4px). Each thread: 4 px x 8 oc (4 oc-pairs).
#define CC 4
__global__ void __launch_bounds__(128,5) tg_conv3x3(
    const float* __restrict__ in0, int C0, long bs0,
    const float* __restrict__ in1A, long bs1A,
    const float* __restrict__ in1B, long bs1B,
    const float* __restrict__ wA, const float* __restrict__ bA,
    const float* __restrict__ wB, const float* __restrict__ bB,
    int nA8, int Cin, int mode,
    const float* __restrict__ hp, long hbs,
    float* __restrict__ cbuf, float* __restrict__ obuf,
    const float* __restrict__ tgp, const float* __restrict__ tdh,
    const float* __restrict__ tdm)
{
  __shared__ __align__(16) float tile[3][CC][720];   // 10 rows x 72 cols, px0 at col 4
  __shared__ __align__(16) u64   ws[2][CC][4][12];   // [pair][ky][kx(pad4)] oc-pair packed

  const int tid = threadIdx.x;
  const int b   = blockIdx.z;
  int ocb = blockIdx.y;
  const int ty = tid >> 4;          // 0..7
  const int tx = (tid & 15) * 4;    // 0..60
  const int y0 = blockIdx.x * 8;

  const int isA = (ocb < nA8);
  const float* in1; const float* w; const float* bias;
  long bs1;
  if (isA){ in1=in1A; bs1=bs1A; w=wA; bias=bA; }
  else { ocb-=nA8; in1=in1B; bs1=bs1B; w=wB; bias=bB; }

  const float* pin0 = in0 + (long)b*bs0;
  const float* pin1 = in1 + (long)b*bs1;

  // ===== independent prologue (const inputs + smem only) =====
  for (int i=tid; i<240; i+=128){
    int buf = i/80; int rem = i-buf*80; int ci = rem/20; int rr = rem-ci*20;
    int r = rr>>1; int side = rr&1;
    tile[buf][ci][r*72 + (side?68:3)] = 0.f;
  }

  // weight slot descriptors (144 u64 per chunk, 2 slots/thread)
  int wex[2], woff[2], wsts[2];
#pragma unroll
  for (int s=0;s<2;s++){
    int j = tid + s*128;
    wex[s] = (j < 144);
    int jj = wex[s] ? j : 0;
    int ci = jj/36; int rem = jj - ci*36; int p = rem/9; int k = rem - p*9;
    int oc0 = ocb*8 + 2*p;
    woff[s] = (oc0*Cin + ci)*9 + k;
    wsts[s] = (((ci*4)+p)*12 + (k/3)*4 + (k%3))*8;
  }
  const int nch = Cin/CC;
  const int wsBufBytes = CC*4*12*8;  // 1536
  char* wsb = (char*)&ws[0][0][0][0];
  uint32_t tbase = (uint32_t)__cvta_generic_to_shared(&tile[0][0][0]);

  // interior tile slots: 160 16B ops per cin, CC*160 = 640 per chunk, 5/thread exactly
  int sci[5], sso[5], sgo[5];
#pragma unroll
  for (int s=0;s<5;s++){
    int idx = tid + s*128;          // 0..639
    int ci  = idx / 160;
    int rem = idx - ci*160;
    int row = rem >> 4;
    int seg = rem & 15;
    int gy  = y0 + row - 1;
    sci[s] = ci;
    sso[s] = ci*2880 + (row*72 + 4 + seg*4)*4;
    sgo[s] = (gy>=0 && gy<64) ? (gy*64 + seg*4) : -1;
  }

  u64 acc[4][4];
#pragma unroll
  for (int p=0;p<4;p++){
    u64 bb = pk2(bias[ocb*8+2*p], bias[ocb*8+2*p+1]);
#pragma unroll
    for (int px=0;px<4;px++) acc[p][px] = bb;
  }

  // weights are const inputs -> safe before gridsync
  float wh[2][2];
#pragma unroll
  for (int s=0;s<2;s++) if (wex[s]){   // chunk 0 weights: LDG + STS now
    float a0 = w[woff[s]];
    float a1 = w[woff[s] + Cin*9];
    *(u64*)(wsb + wsts[s]) = pk2(a0, a1);
  }
#pragma unroll
  for (int s=0;s<2;s++) if (wex[s]){   // chunk 1 weights: LDG, hold
    wh[s][0] = w[woff[s] + 9*CC];
    wh[s][1] = w[woff[s] + 9*CC + Cin*9];
  }

  // ===== wait for predecessor kernel's data =====
  cudaGridDependencySynchronize();

  // ---- dependent prologue: tile chunks 0,1 ----
#pragma unroll 1
  for (int cc=0; cc<2; cc++){
#pragma unroll
    for (int s=0;s<5;s++){
      int cing = cc*CC + sci[s];
      const float* src = (cing < C0) ? pin0 + (long)cing*HW
                                     : pin1 + (long)(cing-C0)*HW;
      cpa16(tbase + (uint32_t)(cc*11520) + sso[s],
            src + (sgo[s]>=0 ? sgo[s] : 0), sgo[s]>=0 ? 16 : 0);
    }
    cpcommit();
  }

  // ---- main pipeline ----
  for (int c=0; c<nch; c++){
    if (c+1 < nch) cpwait1(); else cpwait0();
    __syncthreads();
    if (c+1 < nch){
#pragma unroll
      for (int s=0;s<2;s++) if (wex[s])
        *(u64*)(wsb + ((c+1)&1)*wsBufBytes + wsts[s]) = pk2(wh[s][0], wh[s][1]);
    }
    if (c+2 < nch){
#pragma unroll
      for (int s=0;s<2;s++) if (wex[s]){
        wh[s][0] = w[woff[s] + (c+2)*9*CC];
        wh[s][1] = w[woff[s] + (c+2)*9*CC + Cin*9];
      }
      int buf = (c+2)%3;
#pragma unroll
      for (int s=0;s<5;s++){
        int cing = (c+2)*CC + sci[s];
        const float* src = (cing < C0) ? pin0 + (long)cing*HW
                                       : pin1 + (long)(cing-C0)*HW;
        cpa16(tbase + (uint32_t)(buf*11520) + sso[s],
              src + (sgo[s]>=0 ? sgo[s] : 0), sgo[s]>=0 ? 16 : 0);
      }
      cpcommit();
    }
    // compute chunk c
    const int tb = c%3, wb = c&1;
#pragma unroll
    for (int ci=0;ci<CC;ci++){
#pragma unroll
      for (int r=0;r<3;r++){
        const float* row = &tile[tb][ci][(ty+r)*72 + tx + 3];
        float v0 = row[0];
        float4 vm = *reinterpret_cast<const float4*>(row+1);
        float v5 = row[5];
        u64 pv0=dup2(v0), pv1=dup2(vm.x), pv2=dup2(vm.y),
            pv3=dup2(vm.z), pv4=dup2(vm.w), pv5=dup2(v5);
#pragma unroll
        for (int p=0;p<4;p++){
          ulonglong2 w01 = *reinterpret_cast<const ulonglong2*>(&ws[wb][ci][p][r*4]);
          u64 w2 = ws[wb][ci][p][r*4+2];
          fma2(acc[p][0], w01.x, pv0); fma2(acc[p][0], w01.y, pv1); fma2(acc[p][0], w2, pv2);
          fma2(acc[p][1], w01.x, pv1); fma2(acc[p][1], w01.y, pv2); fma2(acc[p][1], w2, pv3);
          fma2(acc[p][2], w01.x, pv2); fma2(acc[p][2], w01.y, pv3); fma2(acc[p][2], w2, pv4);
          fma2(acc[p][3], w01.x, pv3); fma2(acc[p][3], w01.y, pv4); fma2(acc[p][3], w2, pv5);
        }
      }
    }
  }

  // ---- fused epilogue ----
  const long pixb = (long)(y0+ty)*64 + tx;
  const int seg = ocb >> 3;
#pragma unroll
  for (int p=0;p<4;p++){
    float2 a0=upk(acc[p][0]), a1=upk(acc[p][1]), a2=upk(acc[p][2]), a3=upk(acc[p][3]);
    float av[2][4] = {{a0.x,a1.x,a2.x,a3.x},{a0.y,a1.y,a2.y,a3.y}};
#pragma unroll
    for (int k=0;k<2;k++){
      int oc = ocb*8 + 2*p + k;
      int ch = oc & 63;
      long idx = (long)b*CHW + (long)ch*HW + pixb;
      if (mode == 0){
        if (isA){
          if (seg < 2){
            float gate = sigf(tgp[ch]);
            float dh = expf(-tdh[ch]);
            float4 hv = *reinterpret_cast<const float4*>(&hp[(long)b*hbs + (long)ch*HW + pixb]);
            float4 g;
            g.x = sigf(av[k][0]*gate + hv.x*dh);
            g.y = sigf(av[k][1]*gate + hv.y*dh);
            g.z = sigf(av[k][2]*gate + hv.z*dh);
            g.w = sigf(av[k][3]*gate + hv.w*dh);
            if (seg == 0){
              *reinterpret_cast<float4*>(&g_r[idx]) = g;
              float4 cv = *reinterpret_cast<const float4*>(&cbuf[idx]);
              *reinterpret_cast<float4*>(&g_rc[idx]) =
                make_float4(g.x*cv.x, g.y*cv.y, g.z*cv.z, g.w*cv.w);
            } else {
              *reinterpret_cast<float4*>(&g_z[idx]) = g;
            }
          } else {
            *reinterpret_cast<float4*>(&obuf[idx]) =
              make_float4(sigf(av[k][0]), sigf(av[k][1]), sigf(av[k][2]), sigf(av[k][3]));
          }
        } else {
          float gate = sigf(tgp[ch]);
          float dm = expf(-tdm[ch]);
          float4 mv = *reinterpret_cast<const float4*>(&g_m[idx]);
          float4 g;
          g.x = sigf(av[k][0]*gate + mv.x*dm);
          g.y = sigf(av[k][1]*gate + mv.y*dm);
          g.z = sigf(av[k][2]*gate + mv.z*dm);
          g.w = sigf(av[k][3]*gate + mv.w*dm);
          if (seg == 0){
            *reinterpret_cast<float4*>(&g_xr[idx]) = g;
            *reinterpret_cast<float4*>(&g_xm[idx]) =
              make_float4(g.x*mv.x, g.y*mv.y, g.z*mv.z, g.w*mv.w);
          } else {
            *reinterpret_cast<float4*>(&g_xz[idx]) = g;
          }
        }
      } else {
        float4 tc = make_float4(tanhf(av[k][0]), tanhf(av[k][1]),
                                tanhf(av[k][2]), tanhf(av[k][3]));
        if (isA){
          float4 zv = *reinterpret_cast<const float4*>(&g_z[idx]);
          float4 cv = *reinterpret_cast<const float4*>(&cbuf[idx]);
          float4 cn;
          cn.x = zv.x*cv.x + (1.f-zv.x)*tc.x;
          cn.y = zv.y*cv.y + (1.f-zv.y)*tc.y;
          cn.z = zv.z*cv.z + (1.f-zv.z)*tc.z;
          cn.w = zv.w*cv.w + (1.f-zv.w)*tc.w;
          *reinterpret_cast<float4*>(&cbuf[idx]) = cn;
          *reinterpret_cast<float4*>(&g_gct[idx]) = tc;
        } else {
          float4 xzv = *reinterpret_cast<const float4*>(&g_xz[idx]);
          float4 mv  = *reinterpret_cast<const float4*>(&g_m[idx]);
          float4 mn;
          mn.x = xzv.x*mv.x + (1.f-xzv.x)*tc.x;
          mn.y = xzv.y*mv.y + (1.f-xzv.y)*tc.y;
          mn.z = xzv.z*mv.z + (1.f-xzv.z)*tc.z;
          mn.w = xzv.w*mv.w + (1.f-xzv.w)*tc.w;
          *reinterpret_cast<float4*>(&g_m[idx]) = mn;
          *reinterpret_cast<float4*>(&g_gmt[idx]) = tc;
        }
      }
    }
  }
}

// ---------------- 1x1 conv (f32x2) with fused h = o*tanh(.) and optional q/k ----
// Block 256 thr, each thread 2 px x 4 oc. grid (8, BATCH, 16)
__global__ void __launch_bounds__(256) tg_conv1x1(
    const float* __restrict__ c, const float* __restrict__ obuf,
    const float* __restrict__ w, const float* __restrict__ bias,
    float* __restrict__ out, long bsOut, int doQK)
{
  __shared__ u64 ws[4*128];
  const int tid = threadIdx.x;
  const int b   = blockIdx.y;
  const int ocg = blockIdx.z;   // group of 4 oc
  // independent prologue: weights are const inputs
  for (int i=tid;i<4*128;i+=256){
    float v = w[(long)(ocg*4)*128 + i];
    ws[i] = pk2(v,v);
  }
  u64 acc[4];
#pragma unroll
  for (int oc=0;oc<4;oc++){
    float bv = bias[ocg*4+oc];
    acc[oc] = pk2(bv,bv);
  }
  __syncthreads();
  cudaGridDependencySynchronize();

  const int pix = (blockIdx.x*256 + tid)*2;
  const long base = (long)b*CHW + pix;
#pragma unroll 8
  for (int cc=0;cc<64;cc++){
    u64 v0 = *reinterpret_cast<const u64*>(&c[base + (long)cc*HW]);
    u64 v1 = *reinterpret_cast<const u64*>(&g_m[base + (long)cc*HW]);
#pragma unroll
    for (int oc=0;oc<4;oc++){
      fma2(acc[oc], ws[oc*128+cc], v0);
      fma2(acc[oc], ws[oc*128+64+cc], v1);
    }
  }
#pragma unroll
  for (int oc=0;oc<4;oc++){
    int ocf = ocg*4+oc;
    long idx = base + (long)ocf*HW;
    float2 ov = *reinterpret_cast<const float2*>(&obuf[idx]);
    float2 a = upk(acc[oc]);
    float2 res;
    res.x = ov.x * tanhf(a.x);
    res.y = ov.y * tanhf(a.y);
    *reinterpret_cast<float2*>(&out[(long)b*bsOut + (long)ocf*HW + pix]) = res;
    if (doQK){
      float2 rv = *reinterpret_cast<const float2*>(&g_r[idx]);
      float2 xr = *reinterpret_cast<const float2*>(&g_xr[idx]);
      float2 cv = *reinterpret_cast<const float2*>(&c[idx]);
      float2 gc = *reinterpret_cast<const float2*>(&g_gct[idx]);
      float2 mv = *reinterpret_cast<const float2*>(&g_m[idx]);
      float2 gm = *reinterpret_cast<const float2*>(&g_gmt[idx]);
      float2 q, k2;
      q.x  = 0.25f*(rv.x + xr.x + cv.x + gc.x);
      q.y  = 0.25f*(rv.y + xr.y + cv.y + gc.y);
      k2.x = 0.25f*(rv.x + xr.x + mv.x + gm.x);
      k2.y = 0.25f*(rv.y + xr.y + mv.y + gm.y);
      *reinterpret_cast<float2*>(&g_q[idx]) = q;
      *reinterpret_cast<float2*>(&g_k[idx]) = k2;
    }
  }
}

// ---------------- attention logits + softmax ----------------
__global__ void tg_attn()
{
  __shared__ float qs[HW];
  __shared__ float red[2];
  __shared__ float logits[64];
  __shared__ float tmp[64];
  const int b = blockIdx.y, i = blockIdx.x, t = threadIdx.x;  // 64 threads
  cudaGridDependencySynchronize();
  const float* qrow = g_q + ((long)b*64 + i)*HW;
  for (int n=t;n<HW;n+=64) qs[n] = qrow[n];
  __syncthreads();
  for (int j=0;j<64;j++){
    const float* krow = g_k + ((long)b*64 + j)*HW;
    float s = 0.f;
    for (int n=t;n<HW;n+=64) s += qs[n]*krow[n];
#pragma unroll
    for (int off=16;off;off>>=1) s += __shfl_down_sync(0xffffffffu, s, off);
    if ((t&31)==0) red[t>>5] = s;
    __syncthreads();
    if (t==0) logits[j] = (red[0]+red[1]) * 0.015625f;
    __syncthreads();
  }
  float xv = logits[t];
  tmp[t] = xv; __syncthreads();
  for (int s2=32; s2; s2>>=1){ if (t<s2) tmp[t] = fmaxf(tmp[t], tmp[t+s2]); __syncthreads(); }
  float mx = tmp[0]; __syncthreads();
  float e = expf(xv - mx);
  tmp[t] = e; __syncthreads();
  for (int s2=32; s2; s2>>=1){ if (t<s2) tmp[t] += tmp[t+s2]; __syncthreads(); }
  g_attn[((long)b*64+i)*64 + t] = e / tmp[0];
}

// ---------------- apply attention ----------------
__global__ void __launch_bounds__(256) tg_apply(float* __restrict__ out)
{
  __shared__ float as[64*64];
  const int b = blockIdx.z, tt = blockIdx.y;
  const int n = blockIdx.x*256 + threadIdx.x;
  cudaGridDependencySynchronize();
  for (int i=threadIdx.x;i<4096;i+=256) as[i] = g_attn[(long)b*4096 + i];
  __syncthreads();
  float acc[64];
#pragma unroll
  for (int c=0;c<64;c++) acc[c]=0.f;
  const float* v = g_hs + (((long)b*TSTEPS + tt)*64)*HW + n;
  for (int d=0; d<64; d++){
    float vv = v[(long)d*HW];
#pragma unroll
    for (int c=0;c<64;c++) acc[c] += as[c*64+d]*vv;
  }
  float* op = out + (((long)b*TSTEPS + tt)*64)*HW + n;
#pragma unroll
  for (int c=0;c<64;c++) op[(long)c*HW] = acc[c];
}

// ---------------- PDL launch helper (main stream) ----------------
template <typename F, typename... Args>
static inline void pdl(F fn, dim3 grid, dim3 block, Args... args)
{
  cudaLaunchConfig_t cfg = {};
  cfg.gridDim = grid;
  cfg.blockDim = block;
  cfg.dynamicSmemBytes = 0;
  cfg.stream = 0;   // legacy default stream
  cudaLaunchAttribute at[1];
  at[0].id = cudaLaunchAttributeProgrammaticStreamSerialization;
  at[0].val.programmaticStreamSerializationAllowed = 1;
  cfg.attrs = at;
  cfg.numAttrs = 1;
  cudaLaunchKernelEx(&cfg, fn, args...);
}

// ---------------- orchestration ----------------
extern "C" void kernel_launch(void* const* d_in, const int* in_sizes, int n_in,
                              void* d_out, int out_size)
{
  (void)in_sizes; (void)n_in; (void)out_size;
  const float* x      = (const float*)d_in[0];
  const float* w_rzo0 = (const float*)d_in[1];
  const float* b_rzo0 = (const float*)d_in[2];
  const float* w_rz0  = (const float*)d_in[3];
  const float* b_rz0  = (const float*)d_in[4];
  const float* w_h0   = (const float*)d_in[5];
  const float* b_h0   = (const float*)d_in[6];
  const float* w_o0   = (const float*)d_in[7];
  const float* b_o0   = (const float*)d_in[8];
  const float* td_h0  = (const float*)d_in[9];
  const float* td_m0  = (const float*)d_in[10];
  const float* tg0    = (const float*)d_in[11];
  const float* w_rzo1 = (const float*)d_in[12];
  const float* b_rzo1 = (const float*)d_in[13];
  const float* w_rz1  = (const float*)d_in[14];
  const float* b_rz1  = (const float*)d_in[15];
  const float* w_h1   = (const float*)d_in[16];
  const float* b_h1   = (const float*)d_in[17];
  const float* w_o1   = (const float*)d_in[18];
  const float* b_o1   = (const float*)d_in[19];
  const float* td_h1  = (const float*)d_in[20];
  const float* td_m1  = (const float*)d_in[21];
  const float* tg1    = (const float*)d_in[22];

  float *p_h0,*p_c0,*p_c1,*p_m,*p_rc,*p_xm,*p_o0,*p_o1,*p_hs,*p_zero;
  cudaGetSymbolAddress((void**)&p_h0,  g_h0);
  cudaGetSymbolAddress((void**)&p_c0,  g_c0);
  cudaGetSymbolAddress((void**)&p_c1,  g_c1);
  cudaGetSymbolAddress((void**)&p_m,   g_m);
  cudaGetSymbolAddress((void**)&p_rc,  g_rc);
  cudaGetSymbolAddress((void**)&p_xm,  g_xm);
  cudaGetSymbolAddress((void**)&p_o0,  g_o0);
  cudaGetSymbolAddress((void**)&p_o1,  g_o1);
  cudaGetSymbolAddress((void**)&p_hs,  g_hs);
  cudaGetSymbolAddress((void**)&p_zero,g_zero);

  // lazy-created side stream + events (resource handles only; per-call work
  // is identical on every invocation)
  static cudaStream_t sB = nullptr;
  static cudaEvent_t evA[TSTEPS], evB[TSTEPS];
  if (!sB){
    cudaStreamCreateWithFlags(&sB, cudaStreamNonBlocking);
    for (int t=0;t<TSTEPS;t++){
      cudaEventCreateWithFlags(&evA[t], cudaEventDisableTiming);
      cudaEventCreateWithFlags(&evB[t], cudaEventDisableTiming);
    }
  }

  const long nbs = (long)CHW;

  tg_zero_states<<<NB/256, 256>>>();

  for (int t=0; t<TSTEPS; t++){
    // ---------- layer 0 (Cin = 16+64 = 80) ----------
    const float* xt = x + (long)t*16*HW;
    const long xbs = (long)TSTEPS*16*HW;
    // L0 gate conv runs concurrently with side-stream L1conv1x1(t-1)
    pdl(tg_conv3x3, dim3(8,40,BATCH), dim3(128),
        xt,16,xbs, (const float*)p_h0,nbs, (const float*)p_m,nbs,
        w_rzo0,b_rzo0, w_rz0,b_rz0, 24, 80, 0, (const float*)p_h0,nbs,
        p_c0, p_o0, tg0, td_h0, td_m0);
    // join: L0cand writes g_m which L1conv1x1(t-1) reads
    if (t > 0) cudaStreamWaitEvent(0, evB[t-1], 0);
    pdl(tg_conv3x3, dim3(8,16,BATCH), dim3(128),
        xt,16,xbs, (const float*)p_rc,nbs, (const float*)p_xm,nbs,
        w_h0,b_h0, w_h0,b_h0, 8, 80, 1, (const float*)p_zero,nbs,
        p_c0, p_o0, tg0, td_h0, td_m0);
    pdl(tg_conv1x1, dim3(8,BATCH,16), dim3(256),
        (const float*)p_c0, (const float*)p_o0, w_o0, b_o0, p_h0, nbs, 0);

    // ---------- layer 1 (Cin = 64+64 = 128) ----------
    const float* h1p = (t==0) ? p_zero : (p_hs + (long)(t-1)*CHW);
    const long h1bs  = (t==0) ? nbs : (long)TSTEPS*CHW;
    pdl(tg_conv3x3, dim3(8,40,BATCH), dim3(128),
        (const float*)p_h0,64,nbs, h1p,h1bs, (const float*)p_m,nbs,
        w_rzo1,b_rzo1, w_rz1,b_rz1, 24, 128, 0, h1p,h1bs,
        p_c1, p_o1, tg1, td_h1, td_m1);
    pdl(tg_conv3x3, dim3(8,16,BATCH), dim3(128),
        (const float*)p_h0,64,nbs, (const float*)p_rc,nbs, (const float*)p_xm,nbs,
        w_h1,b_h1, w_h1,b_h1, 8, 128, 1, (const float*)p_zero,nbs,
        p_c1, p_o1, tg1, td_h1, td_m1);
    // fork: L1conv1x1 on side stream, overlapped with next step's L0 gate conv
    cudaEventRecord(evA[t], 0);
    cudaStreamWaitEvent(sB, evA[t], 0);
    tg_conv1x1<<<dim3(8,BATCH,16), 256, 0, sB>>>(
        (const float*)p_c1, (const float*)p_o1, w_o1, b_o1,
        p_hs + (long)t*CHW, (long)TSTEPS*CHW, (t==TSTEPS-1) ? 1 : 0);
    cudaEventRecord(evB[t], sB);
  }

  cudaStreamWaitEvent(0, evB[TSTEPS-1], 0);
  pdl(tg_attn, dim3(64,BATCH), dim3(64));
  pdl(tg_apply, dim3(16,TSTEPS,BATCH), dim3(256), (float*)d_out);
}

// round 15
// speedup vs baseline: 1.0554x; 1.0247x over previous
#include <cuda_runtime.h>
#include <math.h>
#include <stdint.h>

#define BATCH 4
#define TSTEPS 8
#define HC 64
#define HW 4096
#define CHW (HC*HW)            // 262144
#define NB (BATCH*HC*HW)       // 1048576

typedef unsigned long long u64;

// ---------------- f32x2 packed helpers ----------------
__device__ __forceinline__ u64 pk2(float lo, float hi){
  u64 r; asm("mov.b64 %0, {%1,%2};" : "=l"(r) : "f"(lo), "f"(hi)); return r;
}
__device__ __forceinline__ u64 dup2(float v){
  u64 r; asm("mov.b64 %0, {%1,%1};" : "=l"(r) : "f"(v)); return r;
}
__device__ __forceinline__ void fma2(u64 &acc, u64 a, u64 b){
  asm("fma.rn.f32x2 %0, %1, %2, %0;" : "+l"(acc) : "l"(a), "l"(b));
}
__device__ __forceinline__ float2 upk(u64 v){
  float2 f; asm("mov.b64 {%0,%1}, %2;" : "=f"(f.x), "=f"(f.y) : "l"(v)); return f;
}
// ---------------- cp.async helpers ----------------
__device__ __forceinline__ void cpa16(uint32_t saddr, const float* g, int nbytes){
  asm volatile("cp.async.cg.shared.global [%0], [%1], 16, %2;"
               :: "r"(saddr), "l"(g), "r"(nbytes) : "memory");
}
__device__ __forceinline__ void cpcommit(){ asm volatile("cp.async.commit_group;" ::: "memory"); }
__device__ __forceinline__ void cpwait1(){ asm volatile("cp.async.wait_group 1;" ::: "memory"); }
__device__ __forceinline__ void cpwait0(){ asm volatile("cp.async.wait_group 0;" ::: "memory"); }

// ---------------- device scratch (static) ----------------
__device__ float g_h0[NB];
__device__ float g_c0[NB];
__device__ float g_c1[NB];
__device__ float g_m[NB];
__device__ float g_rc[NB], g_xm[NB];
__device__ float g_r[NB], g_z[NB], g_xr[NB], g_xz[NB];
__device__ float g_o0[NB], g_o1[NB];     // per-layer o (enables stream overlap)
__device__ float g_gct[NB], g_gmt[NB];
__device__ float g_q[NB], g_k[NB];
__device__ float g_attn[BATCH*64*64];
__device__ float g_hs[BATCH*TSTEPS*HC*HW];
__device__ float g_zero[NB];   // NEVER written -> stays zero

__device__ __forceinline__ float sigf(float x){ return 1.f/(1.f+expf(-x)); }

__global__ void tg_zero_states(){
  int i = blockIdx.x*256 + threadIdx.x;
  if (i < NB){ g_h0[i]=0.f; g_c0[i]=0.f; g_c1[i]=0.f; g_m[i]=0.f; }
}

// ---------------- merged dual-stream 3x3 conv with FUSED pointwise epilogue ------
// (R8/R12 geometry; PDL prologue/gridsync; launch_bounds (128,5))
// Block 128 thr = 8 rows x 16 colgroups(4px). Each thread: 4 px x 8 oc (4 oc-pairs).
#define CC 4
__global__ void __launch_bounds__(128,5) tg_conv3x3(
    const float* __restrict__ in0, int C0, long bs0,
    const float* __restrict__ in1A, long bs1A,
    const float* __restrict__ in1B, long bs1B,
    const float* __restrict__ wA, const float* __restrict__ bA,
    const float* __restrict__ wB, const float* __restrict__ bB,
    int nA8, int Cin, int mode,
    const float* __restrict__ hp, long hbs,
    float* __restrict__ cbuf, float* __restrict__ obuf,
    const float* __restrict__ tgp, const float* __restrict__ tdh,
    const float* __restrict__ tdm)
{
  __shared__ __align__(16) float tile[3][CC][720];   // 10 rows x 72 cols, px0 at col 4
  __shared__ __align__(16) u64   ws[2][CC][4][12];   // [pair][ky][kx(pad4)] oc-pair packed

  const int tid = threadIdx.x;
  const int b   = blockIdx.z;
  int ocb = blockIdx.y;
  const int ty = tid >> 4;          // 0..7
  const int tx = (tid & 15) * 4;    // 0..60
  const int y0 = blockIdx.x * 8;

  const int isA = (ocb < nA8);
  const float* in1; const float* w; const float* bias;
  long bs1;
  if (isA){ in1=in1A; bs1=bs1A; w=wA; bias=bA; }
  else { ocb-=nA8; in1=in1B; bs1=bs1B; w=wB; bias=bB; }

  const float* pin0 = in0 + (long)b*bs0;
  const float* pin1 = in1 + (long)b*bs1;

  // ===== independent prologue (const inputs + smem only) =====
  for (int i=tid; i<240; i+=128){
    int buf = i/80; int rem = i-buf*80; int ci = rem/20; int rr = rem-ci*20;
    int r = rr>>1; int side = rr&1;
    tile[buf][ci][r*72 + (side?68:3)] = 0.f;
  }

  // weight slot descriptors (144 u64 per chunk, 2 slots/thread)
  int wex[2], woff[2], wsts[2];
#pragma unroll
  for (int s=0;s<2;s++){
    int j = tid + s*128;
    wex[s] = (j < 144);
    int jj = wex[s] ? j : 0;
    int ci = jj/36; int rem = jj - ci*36; int p = rem/9; int k = rem - p*9;
    int oc0 = ocb*8 + 2*p;
    woff[s] = (oc0*Cin + ci)*9 + k;
    wsts[s] = (((ci*4)+p)*12 + (k/3)*4 + (k%3))*8;
  }
  const int nch = Cin/CC;
  const int wsBufBytes = CC*4*12*8;  // 1536
  char* wsb = (char*)&ws[0][0][0][0];
  uint32_t tbase = (uint32_t)__cvta_generic_to_shared(&tile[0][0][0]);

  // interior tile slots: 160 16B ops per cin, CC*160 = 640 per chunk, 5/thread exactly
  int sci[5], sso[5], sgo[5];
#pragma unroll
  for (int s=0;s<5;s++){
    int idx = tid + s*128;          // 0..639
    int ci  = idx / 160;
    int rem = idx - ci*160;
    int row = rem >> 4;
    int seg = rem & 15;
    int gy  = y0 + row - 1;
    sci[s] = ci;
    sso[s] = ci*2880 + (row*72 + 4 + seg*4)*4;
    sgo[s] = (gy>=0 && gy<64) ? (gy*64 + seg*4) : -1;
  }

  u64 acc[4][4];
#pragma unroll
  for (int p=0;p<4;p++){
    u64 bb = pk2(bias[ocb*8+2*p], bias[ocb*8+2*p+1]);
#pragma unroll
    for (int px=0;px<4;px++) acc[p][px] = bb;
  }

  // weights are const inputs -> safe before gridsync
  float wh[2][2];
#pragma unroll
  for (int s=0;s<2;s++) if (wex[s]){   // chunk 0 weights: LDG + STS now
    float a0 = w[woff[s]];
    float a1 = w[woff[s] + Cin*9];
    *(u64*)(wsb + wsts[s]) = pk2(a0, a1);
  }
#pragma unroll
  for (int s=0;s<2;s++) if (wex[s]){   // chunk 1 weights: LDG, hold
    wh[s][0] = w[woff[s] + 9*CC];
    wh[s][1] = w[woff[s] + 9*CC + Cin*9];
  }

  // ===== wait for predecessor kernel's data =====
  cudaGridDependencySynchronize();

  // ---- dependent prologue: tile chunks 0,1 ----
#pragma unroll 1
  for (int cc=0; cc<2; cc++){
#pragma unroll
    for (int s=0;s<5;s++){
      int cing = cc*CC + sci[s];
      const float* src = (cing < C0) ? pin0 + (long)cing*HW
                                     : pin1 + (long)(cing-C0)*HW;
      cpa16(tbase + (uint32_t)(cc*11520) + sso[s],
            src + (sgo[s]>=0 ? sgo[s] : 0), sgo[s]>=0 ? 16 : 0);
    }
    cpcommit();
  }

  // ---- main pipeline ----
  for (int c=0; c<nch; c++){
    if (c+1 < nch) cpwait1(); else cpwait0();
    __syncthreads();
    if (c+1 < nch){
#pragma unroll
      for (int s=0;s<2;s++) if (wex[s])
        *(u64*)(wsb + ((c+1)&1)*wsBufBytes + wsts[s]) = pk2(wh[s][0], wh[s][1]);
    }
    if (c+2 < nch){
#pragma unroll
      for (int s=0;s<2;s++) if (wex[s]){
        wh[s][0] = w[woff[s] + (c+2)*9*CC];
        wh[s][1] = w[woff[s] + (c+2)*9*CC + Cin*9];
      }
      int buf = (c+2)%3;
#pragma unroll
      for (int s=0;s<5;s++){
        int cing = (c+2)*CC + sci[s];
        const float* src = (cing < C0) ? pin0 + (long)cing*HW
                                       : pin1 + (long)(cing-C0)*HW;
        cpa16(tbase + (uint32_t)(buf*11520) + sso[s],
              src + (sgo[s]>=0 ? sgo[s] : 0), sgo[s]>=0 ? 16 : 0);
      }
      cpcommit();
    }
    // compute chunk c
    const int tb = c%3, wb = c&1;
#pragma unroll
    for (int ci=0;ci<CC;ci++){
#pragma unroll
      for (int r=0;r<3;r++){
        const float* row = &tile[tb][ci][(ty+r)*72 + tx + 3];
        float v0 = row[0];
        float4 vm = *reinterpret_cast<const float4*>(row+1);
        float v5 = row[5];
        u64 pv0=dup2(v0), pv1=dup2(vm.x), pv2=dup2(vm.y),
            pv3=dup2(vm.z), pv4=dup2(vm.w), pv5=dup2(v5);
#pragma unroll
        for (int p=0;p<4;p++){
          ulonglong2 w01 = *reinterpret_cast<const ulonglong2*>(&ws[wb][ci][p][r*4]);
          u64 w2 = ws[wb][ci][p][r*4+2];
          fma2(acc[p][0], w01.x, pv0); fma2(acc[p][0], w01.y, pv1); fma2(acc[p][0], w2, pv2);
          fma2(acc[p][1], w01.x, pv1); fma2(acc[p][1], w01.y, pv2); fma2(acc[p][1], w2, pv3);
          fma2(acc[p][2], w01.x, pv2); fma2(acc[p][2], w01.y, pv3); fma2(acc[p][2], w2, pv4);
          fma2(acc[p][3], w01.x, pv3); fma2(acc[p][3], w01.y, pv4); fma2(acc[p][3], w2, pv5);
        }
      }
    }
  }

  // ---- fused epilogue ----
  const long pixb = (long)(y0+ty)*64 + tx;
  const int seg = ocb >> 3;
#pragma unroll
  for (int p=0;p<4;p++){
    float2 a0=upk(acc[p][0]), a1=upk(acc[p][1]), a2=upk(acc[p][2]), a3=upk(acc[p][3]);
    float av[2][4] = {{a0.x,a1.x,a2.x,a3.x},{a0.y,a1.y,a2.y,a3.y}};
#pragma unroll
    for (int k=0;k<2;k++){
      int oc = ocb*8 + 2*p + k;
      int ch = oc & 63;
      long idx = (long)b*CHW + (long)ch*HW + pixb;
      if (mode == 0){
        if (isA){
          if (seg < 2){
            float gate = sigf(tgp[ch]);
            float dh = expf(-tdh[ch]);
            float4 hv = *reinterpret_cast<const float4*>(&hp[(long)b*hbs + (long)ch*HW + pixb]);
            float4 g;
            g.x = sigf(av[k][0]*gate + hv.x*dh);
            g.y = sigf(av[k][1]*gate + hv.y*dh);
            g.z = sigf(av[k][2]*gate + hv.z*dh);
            g.w = sigf(av[k][3]*gate + hv.w*dh);
            if (seg == 0){
              *reinterpret_cast<float4*>(&g_r[idx]) = g;
              float4 cv = *reinterpret_cast<const float4*>(&cbuf[idx]);
              *reinterpret_cast<float4*>(&g_rc[idx]) =
                make_float4(g.x*cv.x, g.y*cv.y, g.z*cv.z, g.w*cv.w);
            } else {
              *reinterpret_cast<float4*>(&g_z[idx]) = g;
            }
          } else {
            *reinterpret_cast<float4*>(&obuf[idx]) =
              make_float4(sigf(av[k][0]), sigf(av[k][1]), sigf(av[k][2]), sigf(av[k][3]));
          }
        } else {
          float gate = sigf(tgp[ch]);
          float dm = expf(-tdm[ch]);
          float4 mv = *reinterpret_cast<const float4*>(&g_m[idx]);
          float4 g;
          g.x = sigf(av[k][0]*gate + mv.x*dm);
          g.y = sigf(av[k][1]*gate + mv.y*dm);
          g.z = sigf(av[k][2]*gate + mv.z*dm);
          g.w = sigf(av[k][3]*gate + mv.w*dm);
          if (seg == 0){
            *reinterpret_cast<float4*>(&g_xr[idx]) = g;
            *reinterpret_cast<float4*>(&g_xm[idx]) =
              make_float4(g.x*mv.x, g.y*mv.y, g.z*mv.z, g.w*mv.w);
          } else {
            *reinterpret_cast<float4*>(&g_xz[idx]) = g;
          }
        }
      } else {
        float4 tc = make_float4(tanhf(av[k][0]), tanhf(av[k][1]),
                                tanhf(av[k][2]), tanhf(av[k][3]));
        if (isA){
          float4 zv = *reinterpret_cast<const float4*>(&g_z[idx]);
          float4 cv = *reinterpret_cast<const float4*>(&cbuf[idx]);
          float4 cn;
          cn.x = zv.x*cv.x + (1.f-zv.x)*tc.x;
          cn.y = zv.y*cv.y + (1.f-zv.y)*tc.y;
          cn.z = zv.z*cv.z + (1.f-zv.z)*tc.z;
          cn.w = zv.w*cv.w + (1.f-zv.w)*tc.w;
          *reinterpret_cast<float4*>(&cbuf[idx]) = cn;
          *reinterpret_cast<float4*>(&g_gct[idx]) = tc;
        } else {
          float4 xzv = *reinterpret_cast<const float4*>(&g_xz[idx]);
          float4 mv  = *reinterpret_cast<const float4*>(&g_m[idx]);
          float4 mn;
          mn.x = xzv.x*mv.x + (1.f-xzv.x)*tc.x;
          mn.y = xzv.y*mv.y + (1.f-xzv.y)*tc.y;
          mn.z = xzv.z*mv.z + (1.f-xzv.z)*tc.z;
          mn.w = xzv.w*mv.w + (1.f-xzv.w)*tc.w;
          *reinterpret_cast<float4*>(&g_m[idx]) = mn;
          *reinterpret_cast<float4*>(&g_gmt[idx]) = tc;
        }
      }
    }
  }
}

// ---------------- 1x1 conv (f32x2) with fused h = o*tanh(.) and optional q/k ----
// Block 256 thr, each thread 2 px x 4 oc. grid (8, BATCH, 16)
__global__ void __launch_bounds__(256) tg_conv1x1(
    const float* __restrict__ c, const float* __restrict__ obuf,
    const float* __restrict__ w, const float* __restrict__ bias,
    float* __restrict__ out, long bsOut, int doQK)
{
  __shared__ u64 ws[4*128];
  const int tid = threadIdx.x;
  const int b   = blockIdx.y;
  const int ocg = blockIdx.z;   // group of 4 oc
  // independent prologue: weights are const inputs
  for (int i=tid;i<4*128;i+=256){
    float v = w[(long)(ocg*4)*128 + i];
    ws[i] = pk2(v,v);
  }
  u64 acc[4];
#pragma unroll
  for (int oc=0;oc<4;oc++){
    float bv = bias[ocg*4+oc];
    acc[oc] = pk2(bv,bv);
  }
  __syncthreads();
  cudaGridDependencySynchronize();

  const int pix = (blockIdx.x*256 + tid)*2;
  const long base = (long)b*CHW + pix;
#pragma unroll 8
  for (int cc=0;cc<64;cc++){
    u64 v0 = *reinterpret_cast<const u64*>(&c[base + (long)cc*HW]);
    u64 v1 = *reinterpret_cast<const u64*>(&g_m[base + (long)cc*HW]);
#pragma unroll
    for (int oc=0;oc<4;oc++){
      fma2(acc[oc], ws[oc*128+cc], v0);
      fma2(acc[oc], ws[oc*128+64+cc], v1);
    }
  }
#pragma unroll
  for (int oc=0;oc<4;oc++){
    int ocf = ocg*4+oc;
    long idx = base + (long)ocf*HW;
    float2 ov = *reinterpret_cast<const float2*>(&obuf[idx]);
    float2 a = upk(acc[oc]);
    float2 res;
    res.x = ov.x * tanhf(a.x);
    res.y = ov.y * tanhf(a.y);
    *reinterpret_cast<float2*>(&out[(long)b*bsOut + (long)ocf*HW + pix]) = res;
    if (doQK){
      float2 rv = *reinterpret_cast<const float2*>(&g_r[idx]);
      float2 xr = *reinterpret_cast<const float2*>(&g_xr[idx]);
      float2 cv = *reinterpret_cast<const float2*>(&c[idx]);
      float2 gc = *reinterpret_cast<const float2*>(&g_gct[idx]);
      float2 mv = *reinterpret_cast<const float2*>(&g_m[idx]);
      float2 gm = *reinterpret_cast<const float2*>(&g_gmt[idx]);
      float2 q, k2;
      q.x  = 0.25f*(rv.x + xr.x + cv.x + gc.x);
      q.y  = 0.25f*(rv.y + xr.y + cv.y + gc.y);
      k2.x = 0.25f*(rv.x + xr.x + mv.x + gm.x);
      k2.y = 0.25f*(rv.y + xr.y + mv.y + gm.y);
      *reinterpret_cast<float2*>(&g_q[idx]) = q;
      *reinterpret_cast<float2*>(&g_k[idx]) = k2;
    }
  }
}

// ---------------- attention logits + softmax (warp-per-j, float4) ----------------
// Block 128 thr (4 warps), grid (64, BATCH). Warp w computes j = w, w+4, ... (16 js),
// each as a 4096-dot-product: 32 lanes x 128 float4 FMAs + shfl reduction.
// No block-wide sync inside the j loop (was 2 per j at 64 threads).
__global__ void __launch_bounds__(128) tg_attn()
{
  __shared__ float qs[HW];
  __shared__ float logits[64];
  __shared__ float tmp[64];
  const int b = blockIdx.y, i = blockIdx.x, tid = threadIdx.x;
  const int wid = tid >> 5, lane = tid & 31;
  cudaGridDependencySynchronize();
  const float4* qrow4 = reinterpret_cast<const float4*>(g_q + ((long)b*64 + i)*HW);
  float4* qs4 = reinterpret_cast<float4*>(qs);
  for (int n=tid; n<1024; n+=128) qs4[n] = qrow4[n];
  __syncthreads();

#pragma unroll 1
  for (int jj=0; jj<16; jj++){
    int j = jj*4 + wid;
    const float4* krow4 = reinterpret_cast<const float4*>(g_k + ((long)b*64 + j)*HW);
    float s = 0.f;
#pragma unroll 4
    for (int n=lane; n<1024; n+=32){
      float4 kv = krow4[n];
      float4 qv = qs4[n];
      s += qv.x*kv.x + qv.y*kv.y + qv.z*kv.z + qv.w*kv.w;
    }
#pragma unroll
    for (int off=16; off; off>>=1) s += __shfl_down_sync(0xffffffffu, s, off);
    if (lane == 0) logits[j] = s * 0.015625f;   // 1/sqrt(4096)
  }
  __syncthreads();

  // softmax over 64 logits (threads 0..63 active in trees; full-block syncs)
  float xv = (tid < 64) ? logits[tid] : 0.f;
  if (tid < 64) tmp[tid] = xv;
  __syncthreads();
  for (int s2=32; s2; s2>>=1){ if (tid<s2) tmp[tid] = fmaxf(tmp[tid], tmp[tid+s2]); __syncthreads(); }
  float mx = tmp[0];
  __syncthreads();
  float e = (tid < 64) ? expf(xv - mx) : 0.f;
  if (tid < 64) tmp[tid] = e;
  __syncthreads();
  for (int s2=32; s2; s2>>=1){ if (tid<s2) tmp[tid] += tmp[tid+s2]; __syncthreads(); }
  if (tid < 64) g_attn[((long)b*64+i)*64 + tid] = e / tmp[0];
}

// ---------------- apply attention ----------------
__global__ void __launch_bounds__(256) tg_apply(float* __restrict__ out)
{
  __shared__ float as[64*64];
  const int b = blockIdx.z, tt = blockIdx.y;
  const int n = blockIdx.x*256 + threadIdx.x;
  cudaGridDependencySynchronize();
  for (int i=threadIdx.x;i<4096;i+=256) as[i] = g_attn[(long)b*4096 + i];
  __syncthreads();
  float acc[64];
#pragma unroll
  for (int c=0;c<64;c++) acc[c]=0.f;
  const float* v = g_hs + (((long)b*TSTEPS + tt)*64)*HW + n;
  for (int d=0; d<64; d++){
    float vv = v[(long)d*HW];
#pragma unroll
    for (int c=0;c<64;c++) acc[c] += as[c*64+d]*vv;
  }
  float* op = out + (((long)b*TSTEPS + tt)*64)*HW + n;
#pragma unroll
  for (int c=0;c<64;c++) op[(long)c*HW] = acc[c];
}

// ---------------- PDL launch helper (main stream) ----------------
template <typename F, typename... Args>
static inline void pdl(F fn, dim3 grid, dim3 block, Args... args)
{
  cudaLaunchConfig_t cfg = {};
  cfg.gridDim = grid;
  cfg.blockDim = block;
  cfg.dynamicSmemBytes = 0;
  cfg.stream = 0;   // legacy default stream
  cudaLaunchAttribute at[1];
  at[0].id = cudaLaunchAttributeProgrammaticStreamSerialization;
  at[0].val.programmaticStreamSerializationAllowed = 1;
  cfg.attrs = at;
  cfg.numAttrs = 1;
  cudaLaunchKernelEx(&cfg, fn, args...);
}

// ---------------- orchestration ----------------
extern "C" void kernel_launch(void* const* d_in, const int* in_sizes, int n_in,
                              void* d_out, int out_size)
{
  (void)in_sizes; (void)n_in; (void)out_size;
  const float* x      = (const float*)d_in[0];
  const float* w_rzo0 = (const float*)d_in[1];
  const float* b_rzo0 = (const float*)d_in[2];
  const float* w_rz0  = (const float*)d_in[3];
  const float* b_rz0  = (const float*)d_in[4];
  const float* w_h0   = (const float*)d_in[5];
  const float* b_h0   = (const float*)d_in[6];
  const float* w_o0   = (const float*)d_in[7];
  const float* b_o0   = (const float*)d_in[8];
  const float* td_h0  = (const float*)d_in[9];
  const float* td_m0  = (const float*)d_in[10];
  const float* tg0    = (const float*)d_in[11];
  const float* w_rzo1 = (const float*)d_in[12];
  const float* b_rzo1 = (const float*)d_in[13];
  const float* w_rz1  = (const float*)d_in[14];
  const float* b_rz1  = (const float*)d_in[15];
  const float* w_h1   = (const float*)d_in[16];
  const float* b_h1   = (const float*)d_in[17];
  const float* w_o1   = (const float*)d_in[18];
  const float* b_o1   = (const float*)d_in[19];
  const float* td_h1  = (const float*)d_in[20];
  const float* td_m1  = (const float*)d_in[21];
  const float* tg1    = (const float*)d_in[22];

  float *p_h0,*p_c0,*p_c1,*p_m,*p_rc,*p_xm,*p_o0,*p_o1,*p_hs,*p_zero;
  cudaGetSymbolAddress((void**)&p_h0,  g_h0);
  cudaGetSymbolAddress((void**)&p_c0,  g_c0);
  cudaGetSymbolAddress((void**)&p_c1,  g_c1);
  cudaGetSymbolAddress((void**)&p_m,   g_m);
  cudaGetSymbolAddress((void**)&p_rc,  g_rc);
  cudaGetSymbolAddress((void**)&p_xm,  g_xm);
  cudaGetSymbolAddress((void**)&p_o0,  g_o0);
  cudaGetSymbolAddress((void**)&p_o1,  g_o1);
  cudaGetSymbolAddress((void**)&p_hs,  g_hs);
  cudaGetSymbolAddress((void**)&p_zero,g_zero);

  // lazy-created side stream + events (resource handles only; per-call work
  // is identical on every invocation)
  static cudaStream_t sB = nullptr;
  static cudaEvent_t evA[TSTEPS], evB[TSTEPS];
  if (!sB){
    cudaStreamCreateWithFlags(&sB, cudaStreamNonBlocking);
    for (int t=0;t<TSTEPS;t++){
      cudaEventCreateWithFlags(&evA[t], cudaEventDisableTiming);
      cudaEventCreateWithFlags(&evB[t], cudaEventDisableTiming);
    }
  }

  const long nbs = (long)CHW;

  tg_zero_states<<<NB/256, 256>>>();

  for (int t=0; t<TSTEPS; t++){
    // ---------- layer 0 (Cin = 16+64 = 80) ----------
    const float* xt = x + (long)t*16*HW;
    const long xbs = (long)TSTEPS*16*HW;
    // L0 gate conv runs concurrently with side-stream L1conv1x1(t-1)
    pdl(tg_conv3x3, dim3(8,40,BATCH), dim3(128),
        xt,16,xbs, (const float*)p_h0,nbs, (const float*)p_m,nbs,
        w_rzo0,b_rzo0, w_rz0,b_rz0, 24, 80, 0, (const float*)p_h0,nbs,
        p_c0, p_o0, tg0, td_h0, td_m0);
    // join: L0cand writes g_m which L1conv1x1(t-1) reads
    if (t > 0) cudaStreamWaitEvent(0, evB[t-1], 0);
    pdl(tg_conv3x3, dim3(8,16,BATCH), dim3(128),
        xt,16,xbs, (const float*)p_rc,nbs, (const float*)p_xm,nbs,
        w_h0,b_h0, w_h0,b_h0, 8, 80, 1, (const float*)p_zero,nbs,
        p_c0, p_o0, tg0, td_h0, td_m0);
    pdl(tg_conv1x1, dim3(8,BATCH,16), dim3(256),
        (const float*)p_c0, (const float*)p_o0, w_o0, b_o0, p_h0, nbs, 0);

    // ---------- layer 1 (Cin = 64+64 = 128) ----------
    const float* h1p = (t==0) ? p_zero : (p_hs + (long)(t-1)*CHW);
    const long h1bs  = (t==0) ? nbs : (long)TSTEPS*CHW;
    pdl(tg_conv3x3, dim3(8,40,BATCH), dim3(128),
        (const float*)p_h0,64,nbs, h1p,h1bs, (const float*)p_m,nbs,
        w_rzo1,b_rzo1, w_rz1,b_rz1, 24, 128, 0, h1p,h1bs,
        p_c1, p_o1, tg1, td_h1, td_m1);
    pdl(tg_conv3x3, dim3(8,16,BATCH), dim3(128),
        (const float*)p_h0,64,nbs, (const float*)p_rc,nbs, (const float*)p_xm,nbs,
        w_h1,b_h1, w_h1,b_h1, 8, 128, 1, (const float*)p_zero,nbs,
        p_c1, p_o1, tg1, td_h1, td_m1);
    // fork: L1conv1x1 on side stream, overlapped with next step's L0 gate conv
    cudaEventRecord(evA[t], 0);
    cudaStreamWaitEvent(sB, evA[t], 0);
    tg_conv1x1<<<dim3(8,BATCH,16), 256, 0, sB>>>(
        (const float*)p_c1, (const float*)p_o1, w_o1, b_o1,
        p_hs + (long)t*CHW, (long)TSTEPS*CHW, (t==TSTEPS-1) ? 1 : 0);
    cudaEventRecord(evB[t], sB);
  }

  cudaStreamWaitEvent(0, evB[TSTEPS-1], 0);
  pdl(tg_attn, dim3(64,BATCH), dim3(128));
  pdl(tg_apply, dim3(16,TSTEPS,BATCH), dim3(256), (float*)d_out);
}